// round 13
// baseline (speedup 1.0000x reference)
#include <cuda_runtime.h>
#include <cuda_fp16.h>
#include <math.h>

#define BATCH 32768
#define FEAT  40
#define DCOLS 496
#define NT    1000

__device__ float g_la[NT], g_l1ma[NT], g_lca[NT], g_l1mca[NT];
__device__ float g_cs_part[16][DCOLS];
__device__ float g_colsum[DCOLS];
__device__ float g_row_loss[BATCH];
__device__ double g_part[64];
__device__ __align__(16) unsigned short g_Whalf[DCOLS * DCOLS];   // fp16 copy of W

__constant__ float c_lognc[5] = {0.69314718055994531f, 1.38629436111989062f,
                                 2.07944154167983593f, 2.77258872223978124f,
                                 3.46573590279972655f};
__constant__ int c_off[5] = {0, 2, 6, 14, 30};

#define CLOG (-69.07755278982137f)   // log(1e-30)

// fast logaddexp (rel err ~1e-7, budget is 1e-3)
__device__ __forceinline__ float flae(float a, float b) {
    float mx = fmaxf(a, b);
    return mx + __logf(1.0f + __expf(-fabsf(a - b)));
}

__device__ __forceinline__ float wred(float v) {
    #pragma unroll
    for (int o = 16; o; o >>= 1) v += __shfl_down_sync(0xffffffffu, v, o);
    return v;
}

// ---------------------------------------------------------------------------
// Fused: W -> fp16 conversion + partial column sums (single pass over W).
// ---------------------------------------------------------------------------
__global__ void wcs_kernel(const float* __restrict__ W) {
    int j  = blockIdx.x * 128 + threadIdx.x;
    int r0 = blockIdx.y * 31;
    if (j < DCOLS) {
        float s0 = 0.f;
        #pragma unroll
        for (int d = 0; d < 31; d++) {
            float w0 = W[(size_t)(r0 + d) * DCOLS + j];
            s0 += w0;
            g_Whalf[(size_t)(r0 + d) * DCOLS + j] = __half_as_ushort(__float2half_rn(w0));
        }
        g_cs_part[blockIdx.y][j] = s0;
    }
}

// ---------------------------------------------------------------------------
// Fused: diffusion schedule (block 0) + colsum combine (blocks 1-4).
// ---------------------------------------------------------------------------
__global__ void sched_comb_kernel() {
    if (blockIdx.x == 0) {
        __shared__ float s[1024];
        int t = threadIdx.x;
        float la = 0.0f;
        if (t < NT) {
            float beta = (t == NT - 1) ? 0.02f : (1e-4f + (float)t * ((0.02f - 1e-4f) / 999.0f));
            la = log1pf(-beta);
            g_la[t]   = la;
            g_l1ma[t] = logf(beta);
        }
        s[t] = la;
        __syncthreads();
        for (int off = 1; off < 1024; off <<= 1) {
            float v = (t >= off) ? s[t - off] : 0.0f;
            __syncthreads();
            s[t] += v;
            __syncthreads();
        }
        if (t < NT) {
            float lc = s[t];
            g_lca[t]   = lc;
            g_l1mca[t] = logf(-expm1f(lc));
        }
    } else {
        int j = (blockIdx.x - 1) * 128 + threadIdx.x;
        if (threadIdx.x < 128 && j < DCOLS) {
            float s = 0.f;
            #pragma unroll
            for (int i = 0; i < 16; i++) s += g_cs_part[i][j];
            g_colsum[j] = s;
        }
    }
}

// ---------------------------------------------------------------------------
// Main: one block per batch row, 128 threads.
// Dense phases: thread t (t<124) owns columns 4t..4t+3.
// Scanner: 80 jobs — thread 2f+h scans half h of feature f, shfl-combine.
// ---------------------------------------------------------------------------
__global__ void __launch_bounds__(128, 16) ddpm_kernel(
    const int*   __restrict__ x0,
    const int*   __restrict__ tsteps,
    const float* __restrict__ uni,
    const float* __restrict__ bias,
    const float* __restrict__ temb)
{
    const int b   = blockIdx.x;
    const int tid = threadIdx.x;

    __shared__ __align__(16) float sm[DCOLS];
    __shared__ int    s_col0[FEAT];
    __shared__ int    s_wbyte[FEAT];
    __shared__ float2 s_lp[FEAT];      // {lpo, lp0} q_prior logits
    __shared__ float4 s_fc[FEAT];      // {lse_pred, e0, B, unused} for dense accum
    __shared__ float  s_red[3][4];

    const int   t    = tsteps[b];
    const int   tm1  = (t > 0) ? t - 1 : 0;
    const float lca1 = g_lca[tm1], l1mca1 = g_l1mca[tm1];
    const float Aev  = (t == 0) ? 1.0f : __expf(lca1);     // uniform per block

    // scanner job geometry: tid<80, f = tid>>1, h = tid&1
    const bool     isjob = (tid < 80);
    const bool     isfeat = isjob && ((tid & 1) == 0);
    const unsigned jmask = (tid < 64) ? 0xffffffffu : 0x0000ffffu;
    int f = 0, kcl = 0, start = 0, wdt = 0, hw = 0, hs = 0;
    if (isjob) {
        f = tid >> 1;
        int g = f / 5; kcl = f - 5 * g;
        start = 62 * g + c_off[kcl];
        wdt = 2 << kcl; hw = wdt >> 1;
        hs = start + (tid & 1) * hw;
    }

    // feature-thread persistent state
    int c0 = 0, w = 0;

    // -------- setup: per-feature q_prior logits + x0 column (even job thr) --
    if (isfeat) {
        const float lca = g_lca[t], l1mca = g_l1mca[t];
        float lognc = c_lognc[kcl];
        c0 = start + x0[b * FEAT + f];
        s_col0[f] = c0;
        s_lp[f] = make_float2(flae(CLOG + lca, l1mca - lognc),   // elsewhere
                              flae(lca,        l1mca - lognc));  // at x0 col
    }

    const int  j0  = tid * 4;
    const bool act = (j0 < DCOLS);

    // packed feature ids for this thread's 4 columns
    unsigned int fpack = 0;
    if (act) {
        #pragma unroll
        for (int q = 0; q < 4; q++) {
            int j = j0 + q;
            int g = j / 62, o = j - 62 * g;
            int k = (o < 2) ? 0 : (o < 6) ? 1 : (o < 14) ? 2 : (o < 30) ? 3 : 4;
            fpack |= (unsigned int)(5 * g + k) << (8 * q);
        }
    }
    __syncthreads();

    // -------- phase 1: z = gumbel + q_prior logits --------
    if (act) {
        float4 u4 = *reinterpret_cast<const float4*>(uni + (size_t)b * DCOLS + j0);
        const float* up = reinterpret_cast<const float*>(&u4);
        float4 z; float* zp = reinterpret_cast<float*>(&z);
        #pragma unroll
        for (int q = 0; q < 4; q++) {
            int j = j0 + q;
            int ff = (fpack >> (8 * q)) & 0xff;
            float gum = -__logf(-__logf(up[q] + 1e-30f) + 1e-30f);
            float2 lp = s_lp[ff];
            zp[q] = gum + ((j == s_col0[ff]) ? lp.y : lp.x);
        }
        *reinterpret_cast<float4*>(sm + j0) = z;
    }
    __syncthreads();

    // per-segment argmax: split halves + shfl combine (first-max tiebreak)
    if (isjob) {
        float best; int bi;
        if (hw == 1) {
            best = sm[hs]; bi = hs;
        } else {
            const float2* p2 = reinterpret_cast<const float2*>(sm + hs);
            best = -3.4e38f; bi = hs;
            int n2 = hw >> 1;
            for (int i = 0; i < n2; i++) {
                float2 v = p2[i];
                if (v.x > best) { best = v.x; bi = hs + 2 * i; }
                if (v.y > best) { best = v.y; bi = hs + 2 * i + 1; }
            }
        }
        float ob  = __shfl_xor_sync(jmask, best, 1);
        int   obi = __shfl_xor_sync(jmask, bi, 1);
        if (ob > best || (ob == best && obi < bi)) { best = ob; bi = obi; }
        if (isfeat) {
            w = bi;
            s_wbyte[f] = bi * (DCOLS * 2);     // byte offset into fp16 W
        }
    }
    __syncthreads();

    // -------- phase 2: gather-sum of 40 fp16 W rows (124 thr x 4 cols) -----
    if (act) {
        float ax = 0.f, ay = 0.f, az = 0.f, aw = 0.f;
        const char* Wb = (const char*)g_Whalf + (size_t)j0 * 2;
        #pragma unroll 8
        for (int ff = 0; ff < FEAT; ff++) {
            uint2 v = *reinterpret_cast<const uint2*>(Wb + s_wbyte[ff]);
            float2 f01 = __half22float2(*reinterpret_cast<__half2*>(&v.x));
            float2 f23 = __half22float2(*reinterpret_cast<__half2*>(&v.y));
            ax += f01.x; ay += f01.y; az += f23.x; aw += f23.y;
        }
        float4 cs = *reinterpret_cast<const float4*>(g_colsum + j0);
        float4 bb = *reinterpret_cast<const float4*>(bias + j0);
        float4 te = *reinterpret_cast<const float4*>(temb + (size_t)t * DCOLS + j0);
        float4 pr4;
        pr4.x = CLOG * (cs.x - ax) + bb.x + te.x;
        pr4.y = CLOG * (cs.y - ay) + bb.y + te.y;
        pr4.z = CLOG * (cs.z - az) + bb.z + te.z;
        pr4.w = CLOG * (cs.w - aw) + bb.w + te.w;
        *reinterpret_cast<float4*>(sm + j0) = pr4;
    }
    __syncthreads();

    // -------- scanner: split-half LSE(pred) + closed-form tail --------
    float kl = 0.f, dec = 0.f, pr = 0.f;
    if (isjob) {
        float m_loc, s_loc;
        if (hw == 1) {
            m_loc = sm[hs];
        } else {
            const float2* p2 = reinterpret_cast<const float2*>(sm + hs);
            m_loc = -3.4e38f;
            int n2 = hw >> 1;
            for (int i = 0; i < n2; i++) {
                float2 v = p2[i];
                m_loc = fmaxf(m_loc, fmaxf(v.x, v.y));
            }
        }
        float om = __shfl_xor_sync(jmask, m_loc, 1);
        float m = fmaxf(m_loc, om);
        if (hw == 1) {
            s_loc = __expf(sm[hs] - m);
        } else {
            const float2* p2 = reinterpret_cast<const float2*>(sm + hs);
            s_loc = 0.f;
            int n2 = hw >> 1;
            for (int i = 0; i < n2; i++) {
                float2 v = p2[i];
                s_loc += __expf(v.x - m) + __expf(v.y - m);
            }
        }
        float os = __shfl_xor_sync(jmask, s_loc, 1);

        if (isfeat) {
            float lse = m + __logf(s_loc + os);
            float lognc = c_lognc[kcl];

            // per-feature q_one_timestep values
            const float la = g_la[t], l1ma = g_l1ma[t];
            float q1w = flae(la,        l1ma - lognc);
            float q1o = flae(CLOG + la, l1ma - lognc);

            // true posterior closed form
            float ev0 = (t == 0) ? 0.f  : flae(lca1,        l1mca1 - lognc);
            float evo = (t == 0) ? CLOG : flae(CLOG + lca1, l1mca1 - lognc);
            float un_oo = evo + q1o;
            float e0, e1, e2, klc, sum_p;
            if (c0 == w) {
                float un_b = ev0 + q1w;
                float mm = fmaxf(un_b, un_oo);
                float ss = __expf(un_b - mm) + (float)(wdt - 1) * __expf(un_oo - mm);
                float l2 = mm + __logf(ss);
                float lt1 = un_b - l2, lt0 = un_oo - l2;
                e0 = __expf(lt0); e1 = __expf(lt1); e2 = e1;
                klc = e1 * lt1 + (float)(wdt - 1) * e0 * lt0;
                sum_p = e1 + (float)(wdt - 1) * e0;
            } else {
                float un_c0 = ev0 + q1o;
                float un_w  = evo + q1w;
                float mm = fmaxf(fmaxf(un_c0, un_w), un_oo);
                float ss = __expf(un_c0 - mm) + __expf(un_w - mm) + (float)(wdt - 2) * __expf(un_oo - mm);
                float l2 = mm + __logf(ss);
                float lt0 = un_oo - l2, lt1 = un_c0 - l2, lt2 = un_w - l2;
                e0 = __expf(lt0); e1 = __expf(lt1); e2 = __expf(lt2);
                klc = e1 * lt1 + e2 * lt2 + (float)(wdt - 2) * e0 * lt0;
                sum_p = e1 + e2 + (float)(wdt - 2) * e0;
            }

            // est-posterior pieces at c0 and w + closed-form lse2
            float Bev = (t == 0) ? 0.f : __expf(l1mca1 - lognc);
            float pc0 = sm[c0], pw = sm[w];
            float smw  = __expf(pw  - lse);
            float smc0 = __expf(pc0 - lse);
            float ev_c0 = (t == 0) ? (pc0 - lse) : __logf(fmaf(smc0, Aev, Bev));
            float ev_w  = (t == 0) ? (pw  - lse) : __logf(fmaf(smw,  Aev, Bev));
            float qwE = __expf(q1w), qoE = __expf(q1o);
            float Z = Aev * fmaf(qwE - qoE, smw, qoE) + Bev * (qwE + (float)(wdt - 1) * qoE);
            float lse2 = __logf(Z);

            // scanner-side KL correction and decoder NLL
            float corr, q1c0;
            if (c0 == w) {
                corr = klc + (lse2 - q1o) * sum_p - (e1 - e0) * ev_c0 - (q1w - q1o) * e1;
                q1c0 = q1w;
            } else {
                corr = klc + (lse2 - q1o) * sum_p - (e1 - e0) * ev_c0 - (e2 - e0) * ev_w
                     - (q1w - q1o) * e2;
                q1c0 = q1o;
            }
            kl  = corr;
            dec = lse2 - ev_c0 - q1c0;

            s_fc[f] = make_float4(lse, e0, Bev, 0.f);
        }
    }
    if (tid < 5) {                              // kl_prior: 5 distinct values x 8 groups
        float lognc = c_lognc[tid];
        float wdtf = (float)(2 << tid);
        float lcaT = g_lca[NT - 1], l1mcaT = g_l1mca[NT - 1];
        float lq0 = flae(lcaT,        l1mcaT - lognc);
        float lqo = flae(CLOG + lcaT, l1mcaT - lognc);
        pr = 8.0f * (__expf(lq0) * (lq0 + lognc) + (wdtf - 1.0f) * __expf(lqo) * (lqo + lognc));
    }
    __syncthreads();

    // -------- dense accumulation: kl -= e0 * ev_j over all columns --------
    if (act) {
        float4 pv = *reinterpret_cast<const float4*>(sm + j0);
        const float* pp = reinterpret_cast<const float*>(&pv);
        #pragma unroll
        for (int q = 0; q < 4; q++) {
            int ff = (fpack >> (8 * q)) & 0xff;
            float4 fc = s_fc[ff];
            float lh = pp[q] - fc.x;
            float ev = (t == 0) ? lh : __logf(fmaf(__expf(lh), Aev, fc.z));
            kl -= fc.y * ev;
        }
    }

    float rk = wred(kl), rd = wred(dec), rp = wred(pr);
    int wid = tid >> 5, lane = tid & 31;
    if (lane == 0) { s_red[0][wid] = rk; s_red[1][wid] = rd; s_red[2][wid] = rp; }
    __syncthreads();
    if (tid == 0) {
        float K  = s_red[0][0] + s_red[0][1] + s_red[0][2] + s_red[0][3];
        float Dn = s_red[1][0] + s_red[1][1] + s_red[1][2] + s_red[1][3];
        float P  = s_red[2][0] + s_red[2][1] + s_red[2][2] + s_red[2][3];
        float diff = (t == 0) ? Dn : K;
        g_row_loss[b] = diff * 1000.0f + P;
    }
}

// ---------------------------------------------------------------------------
// Two-stage deterministic mean: 64 blocks x 128 threads, then 1 block of 64.
// ---------------------------------------------------------------------------
__global__ void reduce1_kernel() {
    __shared__ double sd[4];
    int tid = threadIdx.x;                  // 128 threads
    const float4* rl = reinterpret_cast<const float4*>(g_row_loss + blockIdx.x * 512);
    float4 a = rl[tid];
    double s = (double)a.x + (double)a.y + (double)a.z + (double)a.w;
    #pragma unroll
    for (int o = 16; o; o >>= 1) s += __shfl_down_sync(0xffffffffu, s, o);
    if ((tid & 31) == 0) sd[tid >> 5] = s;
    __syncthreads();
    if (tid == 0) g_part[blockIdx.x] = sd[0] + sd[1] + sd[2] + sd[3];
}

__global__ void reduce2_kernel(float* __restrict__ out) {
    int tid = threadIdx.x;                  // 64 threads
    double s = g_part[tid];
    #pragma unroll
    for (int o = 16; o; o >>= 1) s += __shfl_down_sync(0xffffffffu, s, o);
    __shared__ double sd[2];
    if ((tid & 31) == 0) sd[tid >> 5] = s;
    __syncthreads();
    if (tid == 0) out[0] = (float)((sd[0] + sd[1]) / (double)BATCH);
}

extern "C" void kernel_launch(void* const* d_in, const int* in_sizes, int n_in,
                              void* d_out, int out_size)
{
    const int*   x0 = nullptr;  const int*   ts = nullptr;
    const float* un = nullptr;  const float* W  = nullptr;
    const float* bi = nullptr;  const float* te = nullptr;
    for (int i = 0; i < n_in; i++) {
        switch (in_sizes[i]) {
            case BATCH * FEAT:   x0 = (const int*)d_in[i];   break;
            case BATCH:          ts = (const int*)d_in[i];   break;
            case BATCH * DCOLS:  un = (const float*)d_in[i]; break;
            case DCOLS * DCOLS:  W  = (const float*)d_in[i]; break;
            case DCOLS:          bi = (const float*)d_in[i]; break;
            case NT * DCOLS:     te = (const float*)d_in[i]; break;
            default: break;
        }
    }
    float* out = (float*)d_out;

    dim3 gcs(4, 16);
    wcs_kernel<<<gcs, 128>>>(W);          // fp16 W + partial colsums
    sched_comb_kernel<<<5, 1024>>>();     // schedule + colsum combine
    ddpm_kernel<<<BATCH, 128>>>(x0, ts, un, bi, te);
    reduce1_kernel<<<64, 128>>>();        // 512 rows per block
    reduce2_kernel<<<1, 64>>>(out);
}

// round 14
// speedup vs baseline: 1.2901x; 1.2901x over previous
#include <cuda_runtime.h>
#include <cuda_fp16.h>
#include <math.h>

#define BATCH 32768
#define FEAT  40
#define DCOLS 496
#define NT    1000

__device__ float g_la[NT], g_l1ma[NT], g_lca[NT], g_l1mca[NT];
__device__ float g_cs_part[16][DCOLS];
__device__ float g_colsum[DCOLS];
__device__ float g_row_loss[BATCH];
__device__ double g_part[64];
__device__ __align__(16) unsigned short g_Whalf[DCOLS * DCOLS];   // fp16 copy of W

__constant__ float c_lognc[5] = {0.69314718055994531f, 1.38629436111989062f,
                                 2.07944154167983593f, 2.77258872223978124f,
                                 3.46573590279972655f};
__constant__ int c_off[5] = {0, 2, 6, 14, 30};

#define CLOG (-69.07755278982137f)   // log(1e-30)

// fast logaddexp (rel err ~1e-7, budget is 1e-3)
__device__ __forceinline__ float flae(float a, float b) {
    float mx = fmaxf(a, b);
    return mx + __logf(1.0f + __expf(-fabsf(a - b)));
}

__device__ __forceinline__ float wred(float v) {
    #pragma unroll
    for (int o = 16; o; o >>= 1) v += __shfl_down_sync(0xffffffffu, v, o);
    return v;
}

// ---------------------------------------------------------------------------
// Fused: W -> fp16 conversion + partial column sums (single pass over W).
// ---------------------------------------------------------------------------
__global__ void wcs_kernel(const float* __restrict__ W) {
    int j  = blockIdx.x * 128 + threadIdx.x;
    int r0 = blockIdx.y * 31;
    if (j < DCOLS) {
        float s0 = 0.f;
        #pragma unroll
        for (int d = 0; d < 31; d++) {
            float w0 = W[(size_t)(r0 + d) * DCOLS + j];
            s0 += w0;
            g_Whalf[(size_t)(r0 + d) * DCOLS + j] = __half_as_ushort(__float2half_rn(w0));
        }
        g_cs_part[blockIdx.y][j] = s0;
    }
}

// ---------------------------------------------------------------------------
// Fused: diffusion schedule (block 0) + colsum combine (blocks 1-4).
// ---------------------------------------------------------------------------
__global__ void sched_comb_kernel() {
    if (blockIdx.x == 0) {
        __shared__ float s[1024];
        int t = threadIdx.x;
        float la = 0.0f;
        if (t < NT) {
            float beta = (t == NT - 1) ? 0.02f : (1e-4f + (float)t * ((0.02f - 1e-4f) / 999.0f));
            la = log1pf(-beta);
            g_la[t]   = la;
            g_l1ma[t] = logf(beta);
        }
        s[t] = la;
        __syncthreads();
        for (int off = 1; off < 1024; off <<= 1) {
            float v = (t >= off) ? s[t - off] : 0.0f;
            __syncthreads();
            s[t] += v;
            __syncthreads();
        }
        if (t < NT) {
            float lc = s[t];
            g_lca[t]   = lc;
            g_l1mca[t] = logf(-expm1f(lc));
        }
    } else {
        int j = (blockIdx.x - 1) * 128 + threadIdx.x;
        if (threadIdx.x < 128 && j < DCOLS) {
            float s = 0.f;
            #pragma unroll
            for (int i = 0; i < 16; i++) s += g_cs_part[i][j];
            g_colsum[j] = s;
        }
    }
}

// ---------------------------------------------------------------------------
// Main: one block per batch row, 128 threads; thread t owns columns 4t..4t+3.
// ---------------------------------------------------------------------------
__global__ void __launch_bounds__(128, 16) ddpm_kernel(
    const int*   __restrict__ x0,
    const int*   __restrict__ tsteps,
    const float* __restrict__ uni,
    const float* __restrict__ bias,
    const float* __restrict__ temb)
{
    const int b   = blockIdx.x;
    const int tid = threadIdx.x;

    __shared__ __align__(16) float sm[DCOLS];
    __shared__ __align__(16) int s_wbyte[FEAT];
    __shared__ int    s_col0[FEAT];
    __shared__ float2 s_lp[FEAT];      // {lpo, lp0} q_prior logits
    __shared__ float4 s_fc[FEAT];      // {lse_pred, e0, B, unused} for dense accum
    __shared__ float  s_red[3][4];

    const int   t    = tsteps[b];
    const int   tm1  = (t > 0) ? t - 1 : 0;
    const float lca1 = g_lca[tm1], l1mca1 = g_l1mca[tm1];
    const float Aev  = (t == 0) ? 1.0f : __expf(lca1);     // uniform per block

    // scanner-thread persistent state
    int c0 = 0, w = 0;

    // -------- setup: per-feature q_prior logits + x0 column --------
    if (tid < FEAT) {
        const float lca = g_lca[t], l1mca = g_l1mca[t];
        int f = tid, g = f / 5, k = f - 5 * g;
        int start = g * 62 + c_off[k];
        float lognc = c_lognc[k];
        c0 = start + x0[b * FEAT + f];
        s_col0[f] = c0;
        s_lp[f] = make_float2(flae(CLOG + lca, l1mca - lognc),   // elsewhere
                              flae(lca,        l1mca - lognc));  // at x0 col
    }

    const int  j0  = tid * 4;
    const bool act = (j0 < DCOLS);

    // packed feature ids for this thread's 4 columns
    unsigned int fpack = 0;
    if (act) {
        #pragma unroll
        for (int q = 0; q < 4; q++) {
            int j = j0 + q;
            int g = j / 62, o = j - 62 * g;
            int k = (o < 2) ? 0 : (o < 6) ? 1 : (o < 14) ? 2 : (o < 30) ? 3 : 4;
            fpack |= (unsigned int)(5 * g + k) << (8 * q);
        }
    }
    __syncthreads();

    // -------- phase 1: z = gumbel + q_prior logits --------
    if (act) {
        float4 u4 = *reinterpret_cast<const float4*>(uni + (size_t)b * DCOLS + j0);
        const float* up = reinterpret_cast<const float*>(&u4);
        float4 z; float* zp = reinterpret_cast<float*>(&z);
        #pragma unroll
        for (int q = 0; q < 4; q++) {
            int j = j0 + q;
            int f = (fpack >> (8 * q)) & 0xff;
            float gum = -__logf(-__logf(up[q] + 1e-30f) + 1e-30f);
            float2 lp = s_lp[f];
            zp[q] = gum + ((j == s_col0[f]) ? lp.y : lp.x);
        }
        *reinterpret_cast<float4*>(sm + j0) = z;
    }
    __syncthreads();

    // per-segment argmax (first-max tie break; segment starts even -> float2)
    if (tid < FEAT) {
        int f = tid, g = f / 5, k = f - 5 * g;
        int start = g * 62 + c_off[k], n2 = (2 << k) >> 1;
        const float2* p2 = reinterpret_cast<const float2*>(sm + start);
        float best = -3.4e38f; int bi = 0;
        for (int i = 0; i < n2; i++) {
            float2 v = p2[i];
            if (v.x > best) { best = v.x; bi = 2 * i; }
            if (v.y > best) { best = v.y; bi = 2 * i + 1; }
        }
        w = start + bi;
        s_wbyte[f] = w * (DCOLS * 2);          // byte offset into fp16 W
    }
    __syncthreads();

    // -------- phase 2: gather-sum of 40 fp16 W rows ------------------------
    // Packed LDS.128 offset reads (10 instead of 40) + half2 accumulation
    // (2 HADD2 per feature instead of 2 cvt + 4 FADD); two accumulator sets
    // break the dependency chain. fp16 accumulation validated in round 9.
    if (act) {
        const char* Wb = (const char*)g_Whalf + (size_t)j0 * 2;
        __half2 zero = __float2half2_rn(0.f);
        __half2 a01a = zero, a23a = zero, a01b = zero, a23b = zero;
        const uint4* ofs4 = reinterpret_cast<const uint4*>(s_wbyte);
        #pragma unroll
        for (int f4 = 0; f4 < FEAT / 4; f4++) {
            uint4 o = ofs4[f4];
            uint2 v0 = *reinterpret_cast<const uint2*>(Wb + o.x);
            uint2 v1 = *reinterpret_cast<const uint2*>(Wb + o.y);
            uint2 v2 = *reinterpret_cast<const uint2*>(Wb + o.z);
            uint2 v3 = *reinterpret_cast<const uint2*>(Wb + o.w);
            a01a = __hadd2(a01a, *reinterpret_cast<__half2*>(&v0.x));
            a23a = __hadd2(a23a, *reinterpret_cast<__half2*>(&v0.y));
            a01b = __hadd2(a01b, *reinterpret_cast<__half2*>(&v1.x));
            a23b = __hadd2(a23b, *reinterpret_cast<__half2*>(&v1.y));
            a01a = __hadd2(a01a, *reinterpret_cast<__half2*>(&v2.x));
            a23a = __hadd2(a23a, *reinterpret_cast<__half2*>(&v2.y));
            a01b = __hadd2(a01b, *reinterpret_cast<__half2*>(&v3.x));
            a23b = __hadd2(a23b, *reinterpret_cast<__half2*>(&v3.y));
        }
        float2 sa01 = __half22float2(a01a), sa23 = __half22float2(a23a);
        float2 sb01 = __half22float2(a01b), sb23 = __half22float2(a23b);
        float ax = sa01.x + sb01.x, ay = sa01.y + sb01.y;
        float az = sa23.x + sb23.x, aw = sa23.y + sb23.y;
        float4 cs = *reinterpret_cast<const float4*>(g_colsum + j0);
        float4 bb = *reinterpret_cast<const float4*>(bias + j0);
        float4 te = *reinterpret_cast<const float4*>(temb + (size_t)t * DCOLS + j0);
        float4 pr4;
        pr4.x = CLOG * (cs.x - ax) + bb.x + te.x;
        pr4.y = CLOG * (cs.y - ay) + bb.y + te.y;
        pr4.z = CLOG * (cs.z - az) + bb.z + te.z;
        pr4.w = CLOG * (cs.w - aw) + bb.w + te.w;
        *reinterpret_cast<float4*>(sm + j0) = pr4;
    }
    __syncthreads();

    // -------- scanner: lse(pred), true posterior, closed-form lse2, corrections --
    float kl = 0.f, dec = 0.f, pr = 0.f;
    if (tid < FEAT) {
        int f = tid, g = f / 5, k = f - 5 * g;
        int start = g * 62 + c_off[k], wdt = 2 << k, n2 = wdt >> 1;
        float lognc = c_lognc[k];

        const float2* p2 = reinterpret_cast<const float2*>(sm + start);
        float m = -3.4e38f;
        for (int i = 0; i < n2; i++) {
            float2 v = p2[i];
            m = fmaxf(m, fmaxf(v.x, v.y));
        }
        float s = 0.f;
        for (int i = 0; i < n2; i++) {
            float2 v = p2[i];
            s += __expf(v.x - m) + __expf(v.y - m);
        }
        float lse = m + __logf(s);

        // per-feature q_one_timestep values (only scanner needs them)
        const float la = g_la[t], l1ma = g_l1ma[t];
        float q1w = flae(la,        l1ma - lognc);
        float q1o = flae(CLOG + la, l1ma - lognc);

        // true posterior closed form
        float ev0 = (t == 0) ? 0.f  : flae(lca1,        l1mca1 - lognc);
        float evo = (t == 0) ? CLOG : flae(CLOG + lca1, l1mca1 - lognc);
        float un_oo = evo + q1o;
        float e0, e1, e2, klc, sum_p;
        if (c0 == w) {
            float un_b = ev0 + q1w;
            float mm = fmaxf(un_b, un_oo);
            float ss = __expf(un_b - mm) + (float)(wdt - 1) * __expf(un_oo - mm);
            float l2 = mm + __logf(ss);
            float lt1 = un_b - l2, lt0 = un_oo - l2;
            e0 = __expf(lt0); e1 = __expf(lt1); e2 = e1;
            klc = e1 * lt1 + (float)(wdt - 1) * e0 * lt0;
            sum_p = e1 + (float)(wdt - 1) * e0;
        } else {
            float un_c0 = ev0 + q1o;
            float un_w  = evo + q1w;
            float mm = fmaxf(fmaxf(un_c0, un_w), un_oo);
            float ss = __expf(un_c0 - mm) + __expf(un_w - mm) + (float)(wdt - 2) * __expf(un_oo - mm);
            float l2 = mm + __logf(ss);
            float lt0 = un_oo - l2, lt1 = un_c0 - l2, lt2 = un_w - l2;
            e0 = __expf(lt0); e1 = __expf(lt1); e2 = __expf(lt2);
            klc = e1 * lt1 + e2 * lt2 + (float)(wdt - 2) * e0 * lt0;
            sum_p = e1 + e2 + (float)(wdt - 2) * e0;
        }

        // est-posterior pieces at c0 and w + closed-form lse2
        float Bev = (t == 0) ? 0.f : __expf(l1mca1 - lognc);
        float pc0 = sm[c0], pw = sm[w];
        float smw  = __expf(pw  - lse);
        float smc0 = __expf(pc0 - lse);
        float ev_c0 = (t == 0) ? (pc0 - lse) : __logf(fmaf(smc0, Aev, Bev));
        float ev_w  = (t == 0) ? (pw  - lse) : __logf(fmaf(smw,  Aev, Bev));
        float qwE = __expf(q1w), qoE = __expf(q1o);
        float Z = Aev * fmaf(qwE - qoE, smw, qoE) + Bev * (qwE + (float)(wdt - 1) * qoE);
        float lse2 = __logf(Z);

        // scanner-side KL correction and decoder NLL
        float corr, q1c0;
        if (c0 == w) {
            corr = klc + (lse2 - q1o) * sum_p - (e1 - e0) * ev_c0 - (q1w - q1o) * e1;
            q1c0 = q1w;
        } else {
            corr = klc + (lse2 - q1o) * sum_p - (e1 - e0) * ev_c0 - (e2 - e0) * ev_w
                 - (q1w - q1o) * e2;
            q1c0 = q1o;
        }
        kl  = corr;
        dec = lse2 - ev_c0 - q1c0;

        s_fc[f] = make_float4(lse, e0, Bev, 0.f);
    }
    if (tid < 5) {                              // kl_prior: 5 distinct values x 8 groups
        float lognc = c_lognc[tid];
        float wdtf = (float)(2 << tid);
        float lcaT = g_lca[NT - 1], l1mcaT = g_l1mca[NT - 1];
        float lq0 = flae(lcaT,        l1mcaT - lognc);
        float lqo = flae(CLOG + lcaT, l1mcaT - lognc);
        pr = 8.0f * (__expf(lq0) * (lq0 + lognc) + (wdtf - 1.0f) * __expf(lqo) * (lqo + lognc));
    }
    __syncthreads();

    // -------- dense accumulation: kl -= e0 * ev_j over all columns --------
    if (act) {
        float4 pv = *reinterpret_cast<const float4*>(sm + j0);
        const float* pp = reinterpret_cast<const float*>(&pv);
        #pragma unroll
        for (int q = 0; q < 4; q++) {
            int f = (fpack >> (8 * q)) & 0xff;
            float4 fc = s_fc[f];
            float lh = pp[q] - fc.x;
            float ev = (t == 0) ? lh : __logf(fmaf(__expf(lh), Aev, fc.z));
            kl -= fc.y * ev;
        }
    }

    float rk = wred(kl), rd = wred(dec), rp = wred(pr);
    int wid = tid >> 5, lane = tid & 31;
    if (lane == 0) { s_red[0][wid] = rk; s_red[1][wid] = rd; s_red[2][wid] = rp; }
    __syncthreads();
    if (tid == 0) {
        float K  = s_red[0][0] + s_red[0][1] + s_red[0][2] + s_red[0][3];
        float Dn = s_red[1][0] + s_red[1][1] + s_red[1][2] + s_red[1][3];
        float P  = s_red[2][0] + s_red[2][1] + s_red[2][2] + s_red[2][3];
        float diff = (t == 0) ? Dn : K;
        g_row_loss[b] = diff * 1000.0f + P;
    }
}

// ---------------------------------------------------------------------------
// Two-stage deterministic mean: 64 blocks x 128 threads, then 1 block of 64.
// ---------------------------------------------------------------------------
__global__ void reduce1_kernel() {
    __shared__ double sd[4];
    int tid = threadIdx.x;                  // 128 threads
    const float4* rl = reinterpret_cast<const float4*>(g_row_loss + blockIdx.x * 512);
    float4 a = rl[tid];
    double s = (double)a.x + (double)a.y + (double)a.z + (double)a.w;
    #pragma unroll
    for (int o = 16; o; o >>= 1) s += __shfl_down_sync(0xffffffffu, s, o);
    if ((tid & 31) == 0) sd[tid >> 5] = s;
    __syncthreads();
    if (tid == 0) g_part[blockIdx.x] = sd[0] + sd[1] + sd[2] + sd[3];
}

__global__ void reduce2_kernel(float* __restrict__ out) {
    int tid = threadIdx.x;                  // 64 threads
    double s = g_part[tid];
    #pragma unroll
    for (int o = 16; o; o >>= 1) s += __shfl_down_sync(0xffffffffu, s, o);
    __shared__ double sd[2];
    if ((tid & 31) == 0) sd[tid >> 5] = s;
    __syncthreads();
    if (tid == 0) out[0] = (float)((sd[0] + sd[1]) / (double)BATCH);
}

extern "C" void kernel_launch(void* const* d_in, const int* in_sizes, int n_in,
                              void* d_out, int out_size)
{
    const int*   x0 = nullptr;  const int*   ts = nullptr;
    const float* un = nullptr;  const float* W  = nullptr;
    const float* bi = nullptr;  const float* te = nullptr;
    for (int i = 0; i < n_in; i++) {
        switch (in_sizes[i]) {
            case BATCH * FEAT:   x0 = (const int*)d_in[i];   break;
            case BATCH:          ts = (const int*)d_in[i];   break;
            case BATCH * DCOLS:  un = (const float*)d_in[i]; break;
            case DCOLS * DCOLS:  W  = (const float*)d_in[i]; break;
            case DCOLS:          bi = (const float*)d_in[i]; break;
            case NT * DCOLS:     te = (const float*)d_in[i]; break;
            default: break;
        }
    }
    float* out = (float*)d_out;

    dim3 gcs(4, 16);
    wcs_kernel<<<gcs, 128>>>(W);          // fp16 W + partial colsums
    sched_comb_kernel<<<5, 1024>>>();     // schedule + colsum combine
    ddpm_kernel<<<BATCH, 128>>>(x0, ts, un, bi, te);
    reduce1_kernel<<<64, 128>>>();        // 512 rows per block
    reduce2_kernel<<<1, 64>>>(out);
}

// round 16
// speedup vs baseline: 1.3128x; 1.0175x over previous
#include <cuda_runtime.h>
#include <cuda_fp16.h>
#include <math.h>

#define BATCH 32768
#define FEAT  40
#define DCOLS 496
#define NT    1000

__device__ float g_la[NT], g_l1ma[NT], g_lca[NT], g_l1mca[NT];
__device__ float g_cs_part[16][DCOLS];
__device__ float g_colsum[DCOLS];
__device__ double g_accum;
__device__ __align__(16) unsigned short g_Whalf[DCOLS * DCOLS];   // fp16 copy of W

__constant__ float c_lognc[5] = {0.69314718055994531f, 1.38629436111989062f,
                                 2.07944154167983593f, 2.77258872223978124f,
                                 3.46573590279972655f};
__constant__ int c_off[5] = {0, 2, 6, 14, 30};

#define CLOG (-69.07755278982137f)   // log(1e-30)

// fast logaddexp (rel err ~1e-7, budget is 1e-3)
__device__ __forceinline__ float flae(float a, float b) {
    float mx = fmaxf(a, b);
    return mx + __logf(1.0f + __expf(-fabsf(a - b)));
}

__device__ __forceinline__ __half2 u2h2(unsigned int u) {
    return *reinterpret_cast<__half2*>(&u);
}

__device__ __forceinline__ float wred(float v) {
    #pragma unroll
    for (int o = 16; o; o >>= 1) v += __shfl_down_sync(0xffffffffu, v, o);
    return v;
}

// ---------------------------------------------------------------------------
// Fused: W -> fp16 conversion + partial column sums (single pass over W).
// ---------------------------------------------------------------------------
__global__ void wcs_kernel(const float* __restrict__ W) {
    int j  = blockIdx.x * 128 + threadIdx.x;
    int r0 = blockIdx.y * 31;
    if (j < DCOLS) {
        float s0 = 0.f;
        #pragma unroll
        for (int d = 0; d < 31; d++) {
            float w0 = W[(size_t)(r0 + d) * DCOLS + j];
            s0 += w0;
            g_Whalf[(size_t)(r0 + d) * DCOLS + j] = __half_as_ushort(__float2half_rn(w0));
        }
        g_cs_part[blockIdx.y][j] = s0;
    }
}

// ---------------------------------------------------------------------------
// Fused: diffusion schedule (block 0) + colsum combine (blocks 1-4).
// Also zeroes the loss accumulator each launch (before ddpm in-stream).
// ---------------------------------------------------------------------------
__global__ void sched_comb_kernel() {
    if (blockIdx.x == 0) {
        __shared__ float s[1024];
        int t = threadIdx.x;
        if (t == 0) g_accum = 0.0;
        float la = 0.0f;
        if (t < NT) {
            float beta = (t == NT - 1) ? 0.02f : (1e-4f + (float)t * ((0.02f - 1e-4f) / 999.0f));
            la = log1pf(-beta);
            g_la[t]   = la;
            g_l1ma[t] = logf(beta);
        }
        s[t] = la;
        __syncthreads();
        for (int off = 1; off < 1024; off <<= 1) {
            float v = (t >= off) ? s[t - off] : 0.0f;
            __syncthreads();
            s[t] += v;
            __syncthreads();
        }
        if (t < NT) {
            float lc = s[t];
            g_lca[t]   = lc;
            g_l1mca[t] = logf(-expm1f(lc));
        }
    } else {
        int j = (blockIdx.x - 1) * 128 + threadIdx.x;
        if (threadIdx.x < 128 && j < DCOLS) {
            float s = 0.f;
            #pragma unroll
            for (int i = 0; i < 16; i++) s += g_cs_part[i][j];
            g_colsum[j] = s;
        }
    }
}

// ---------------------------------------------------------------------------
// Main: one block per batch row, 128 threads; thread t owns columns 4t..4t+3.
// Gather: split-feature scheme — thread g<62 loads features 0-19 for col-group
// g (8 cols, LDG.128); thread 62<=g<124 loads features 20-39 for col-group
// g-62. Partials combine through SMEM.
// ---------------------------------------------------------------------------
__global__ void __launch_bounds__(128, 16) ddpm_kernel(
    const int*   __restrict__ x0,
    const int*   __restrict__ tsteps,
    const float* __restrict__ uni,
    const float* __restrict__ bias,
    const float* __restrict__ temb)
{
    const int b   = blockIdx.x;
    const int tid = threadIdx.x;

    __shared__ __align__(16) float sm[DCOLS];
    __shared__ __align__(16) int s_wbyte[FEAT];
    __shared__ __align__(16) uint4 s_part[2][62];
    __shared__ int    s_col0[FEAT];
    __shared__ float2 s_lp[FEAT];      // {lpo, lp0} q_prior logits
    __shared__ float4 s_fc[FEAT];      // {lse_pred, e0, B, unused} for dense accum
    __shared__ float  s_red[3][4];

    const int   t    = tsteps[b];
    const int   tm1  = (t > 0) ? t - 1 : 0;
    const float lca1 = g_lca[tm1], l1mca1 = g_l1mca[tm1];
    const float Aev  = (t == 0) ? 1.0f : __expf(lca1);     // uniform per block

    // scanner-thread persistent state
    int c0 = 0, w = 0;

    // -------- setup: per-feature q_prior logits + x0 column --------
    if (tid < FEAT) {
        const float lca = g_lca[t], l1mca = g_l1mca[t];
        int f = tid, g = f / 5, k = f - 5 * g;
        int start = g * 62 + c_off[k];
        float lognc = c_lognc[k];
        c0 = start + x0[b * FEAT + f];
        s_col0[f] = c0;
        s_lp[f] = make_float2(flae(CLOG + lca, l1mca - lognc),   // elsewhere
                              flae(lca,        l1mca - lognc));  // at x0 col
    }

    const int  j0  = tid * 4;
    const bool act = (j0 < DCOLS);

    // packed feature ids for this thread's 4 columns
    unsigned int fpack = 0;
    if (act) {
        #pragma unroll
        for (int q = 0; q < 4; q++) {
            int j = j0 + q;
            int g = j / 62, o = j - 62 * g;
            int k = (o < 2) ? 0 : (o < 6) ? 1 : (o < 14) ? 2 : (o < 30) ? 3 : 4;
            fpack |= (unsigned int)(5 * g + k) << (8 * q);
        }
    }
    __syncthreads();

    // -------- phase 1: z = gumbel + q_prior logits --------
    if (act) {
        float4 u4 = *reinterpret_cast<const float4*>(uni + (size_t)b * DCOLS + j0);
        const float* up = reinterpret_cast<const float*>(&u4);
        float4 z; float* zp = reinterpret_cast<float*>(&z);
        #pragma unroll
        for (int q = 0; q < 4; q++) {
            int j = j0 + q;
            int f = (fpack >> (8 * q)) & 0xff;
            float gum = -__logf(-__logf(up[q] + 1e-30f) + 1e-30f);
            float2 lp = s_lp[f];
            zp[q] = gum + ((j == s_col0[f]) ? lp.y : lp.x);
        }
        *reinterpret_cast<float4*>(sm + j0) = z;
    }
    __syncthreads();

    // per-segment argmax (first-max tie break; segment starts even -> float2)
    if (tid < FEAT) {
        int f = tid, g = f / 5, k = f - 5 * g;
        int start = g * 62 + c_off[k], n2 = (2 << k) >> 1;
        const float2* p2 = reinterpret_cast<const float2*>(sm + start);
        float best = -3.4e38f; int bi = 0;
        for (int i = 0; i < n2; i++) {
            float2 v = p2[i];
            if (v.x > best) { best = v.x; bi = 2 * i; }
            if (v.y > best) { best = v.y; bi = 2 * i + 1; }
        }
        w = start + bi;
        s_wbyte[f] = w * (DCOLS * 2);          // byte offset into fp16 W
    }
    __syncthreads();

    // -------- phase 2a: split-feature gather (124 thr, LDG.128) -----------
    if (act) {
        int c = (tid < 62) ? tid : tid - 62;           // col-group: cols 8c..8c+7
        int h = (tid < 62) ? 0 : 1;                    // feature half
        const char* Wb = (const char*)g_Whalf + c * 16;
        __half2 zero = __float2half2_rn(0.f);
        __half2 a0 = zero, a1 = zero, a2 = zero, a3 = zero;
        const uint4* ofs4 = reinterpret_cast<const uint4*>(s_wbyte + h * 20);
        #pragma unroll
        for (int f4 = 0; f4 < 5; f4++) {
            uint4 o = ofs4[f4];
            uint4 v0 = *reinterpret_cast<const uint4*>(Wb + o.x);
            uint4 v1 = *reinterpret_cast<const uint4*>(Wb + o.y);
            uint4 v2 = *reinterpret_cast<const uint4*>(Wb + o.z);
            uint4 v3 = *reinterpret_cast<const uint4*>(Wb + o.w);
            a0 = __hadd2(a0, u2h2(v0.x)); a1 = __hadd2(a1, u2h2(v0.y));
            a2 = __hadd2(a2, u2h2(v0.z)); a3 = __hadd2(a3, u2h2(v0.w));
            a0 = __hadd2(a0, u2h2(v1.x)); a1 = __hadd2(a1, u2h2(v1.y));
            a2 = __hadd2(a2, u2h2(v1.z)); a3 = __hadd2(a3, u2h2(v1.w));
            a0 = __hadd2(a0, u2h2(v2.x)); a1 = __hadd2(a1, u2h2(v2.y));
            a2 = __hadd2(a2, u2h2(v2.z)); a3 = __hadd2(a3, u2h2(v2.w));
            a0 = __hadd2(a0, u2h2(v3.x)); a1 = __hadd2(a1, u2h2(v3.y));
            a2 = __hadd2(a2, u2h2(v3.z)); a3 = __hadd2(a3, u2h2(v3.w));
        }
        uint4 o;
        o.x = *reinterpret_cast<unsigned int*>(&a0);
        o.y = *reinterpret_cast<unsigned int*>(&a1);
        o.z = *reinterpret_cast<unsigned int*>(&a2);
        o.w = *reinterpret_cast<unsigned int*>(&a3);
        s_part[h][c] = o;
    }
    __syncthreads();

    // -------- phase 2b: combine halves + pred (124 thr x 4 cols) ----------
    if (act) {
        int c = tid >> 1, sel = tid & 1;
        const uint2* p0 = reinterpret_cast<const uint2*>(&s_part[0][c]) + sel;
        const uint2* p1 = reinterpret_cast<const uint2*>(&s_part[1][c]) + sel;
        uint2 u0 = *p0, u1 = *p1;
        __half2 c01 = __hadd2(u2h2(u0.x), u2h2(u1.x));
        __half2 c23 = __hadd2(u2h2(u0.y), u2h2(u1.y));
        float2 f01 = __half22float2(c01), f23 = __half22float2(c23);
        float4 cs = *reinterpret_cast<const float4*>(g_colsum + j0);
        float4 bb = *reinterpret_cast<const float4*>(bias + j0);
        float4 te = *reinterpret_cast<const float4*>(temb + (size_t)t * DCOLS + j0);
        float4 pr4;
        pr4.x = CLOG * (cs.x - f01.x) + bb.x + te.x;
        pr4.y = CLOG * (cs.y - f01.y) + bb.y + te.y;
        pr4.z = CLOG * (cs.z - f23.x) + bb.z + te.z;
        pr4.w = CLOG * (cs.w - f23.y) + bb.w + te.w;
        *reinterpret_cast<float4*>(sm + j0) = pr4;
    }
    __syncthreads();

    // -------- scanner: lse(pred), true posterior, closed-form lse2, corrections --
    float kl = 0.f, dec = 0.f, pr = 0.f;
    if (tid < FEAT) {
        int f = tid, g = f / 5, k = f - 5 * g;
        int start = g * 62 + c_off[k], wdt = 2 << k, n2 = wdt >> 1;
        float lognc = c_lognc[k];

        const float2* p2 = reinterpret_cast<const float2*>(sm + start);
        float m = -3.4e38f;
        for (int i = 0; i < n2; i++) {
            float2 v = p2[i];
            m = fmaxf(m, fmaxf(v.x, v.y));
        }
        float s = 0.f;
        for (int i = 0; i < n2; i++) {
            float2 v = p2[i];
            s += __expf(v.x - m) + __expf(v.y - m);
        }
        float lse = m + __logf(s);

        // per-feature q_one_timestep values (only scanner needs them)
        const float la = g_la[t], l1ma = g_l1ma[t];
        float q1w = flae(la,        l1ma - lognc);
        float q1o = flae(CLOG + la, l1ma - lognc);

        // true posterior closed form
        float ev0 = (t == 0) ? 0.f  : flae(lca1,        l1mca1 - lognc);
        float evo = (t == 0) ? CLOG : flae(CLOG + lca1, l1mca1 - lognc);
        float un_oo = evo + q1o;
        float e0, e1, e2, klc, sum_p;
        if (c0 == w) {
            float un_b = ev0 + q1w;
            float mm = fmaxf(un_b, un_oo);
            float ss = __expf(un_b - mm) + (float)(wdt - 1) * __expf(un_oo - mm);
            float l2 = mm + __logf(ss);
            float lt1 = un_b - l2, lt0 = un_oo - l2;
            e0 = __expf(lt0); e1 = __expf(lt1); e2 = e1;
            klc = e1 * lt1 + (float)(wdt - 1) * e0 * lt0;
            sum_p = e1 + (float)(wdt - 1) * e0;
        } else {
            float un_c0 = ev0 + q1o;
            float un_w  = evo + q1w;
            float mm = fmaxf(fmaxf(un_c0, un_w), un_oo);
            float ss = __expf(un_c0 - mm) + __expf(un_w - mm) + (float)(wdt - 2) * __expf(un_oo - mm);
            float l2 = mm + __logf(ss);
            float lt0 = un_oo - l2, lt1 = un_c0 - l2, lt2 = un_w - l2;
            e0 = __expf(lt0); e1 = __expf(lt1); e2 = __expf(lt2);
            klc = e1 * lt1 + e2 * lt2 + (float)(wdt - 2) * e0 * lt0;
            sum_p = e1 + e2 + (float)(wdt - 2) * e0;
        }

        // est-posterior pieces at c0 and w + closed-form lse2
        float Bev = (t == 0) ? 0.f : __expf(l1mca1 - lognc);
        float pc0 = sm[c0], pw = sm[w];
        float smw  = __expf(pw  - lse);
        float smc0 = __expf(pc0 - lse);
        float ev_c0 = (t == 0) ? (pc0 - lse) : __logf(fmaf(smc0, Aev, Bev));
        float ev_w  = (t == 0) ? (pw  - lse) : __logf(fmaf(smw,  Aev, Bev));
        float qwE = __expf(q1w), qoE = __expf(q1o);
        float Z = Aev * fmaf(qwE - qoE, smw, qoE) + Bev * (qwE + (float)(wdt - 1) * qoE);
        float lse2 = __logf(Z);

        // scanner-side KL correction and decoder NLL
        float corr, q1c0;
        if (c0 == w) {
            corr = klc + (lse2 - q1o) * sum_p - (e1 - e0) * ev_c0 - (q1w - q1o) * e1;
            q1c0 = q1w;
        } else {
            corr = klc + (lse2 - q1o) * sum_p - (e1 - e0) * ev_c0 - (e2 - e0) * ev_w
                 - (q1w - q1o) * e2;
            q1c0 = q1o;
        }
        kl  = corr;
        dec = lse2 - ev_c0 - q1c0;

        s_fc[f] = make_float4(lse, e0, Bev, 0.f);
    }
    if (tid < 5) {                              // kl_prior: 5 distinct values x 8 groups
        float lognc = c_lognc[tid];
        float wdtf = (float)(2 << tid);
        float lcaT = g_lca[NT - 1], l1mcaT = g_l1mca[NT - 1];
        float lq0 = flae(lcaT,        l1mcaT - lognc);
        float lqo = flae(CLOG + lcaT, l1mcaT - lognc);
        pr = 8.0f * (__expf(lq0) * (lq0 + lognc) + (wdtf - 1.0f) * __expf(lqo) * (lqo + lognc));
    }
    __syncthreads();

    // -------- dense accumulation: kl -= e0 * ev_j over all columns --------
    if (act) {
        float4 pv = *reinterpret_cast<const float4*>(sm + j0);
        const float* pp = reinterpret_cast<const float*>(&pv);
        #pragma unroll
        for (int q = 0; q < 4; q++) {
            int f = (fpack >> (8 * q)) & 0xff;
            float4 fc = s_fc[f];
            float lh = pp[q] - fc.x;
            float ev = (t == 0) ? lh : __logf(fmaf(__expf(lh), Aev, fc.z));
            kl -= fc.y * ev;
        }
    }

    float rk = wred(kl), rd = wred(dec), rp = wred(pr);
    int wid = tid >> 5, lane = tid & 31;
    if (lane == 0) { s_red[0][wid] = rk; s_red[1][wid] = rd; s_red[2][wid] = rp; }
    __syncthreads();
    if (tid == 0) {
        float K  = s_red[0][0] + s_red[0][1] + s_red[0][2] + s_red[0][3];
        float Dn = s_red[1][0] + s_red[1][1] + s_red[1][2] + s_red[1][3];
        float P  = s_red[2][0] + s_red[2][1] + s_red[2][2] + s_red[2][3];
        float diff = (t == 0) ? Dn : K;
        atomicAdd(&g_accum, (double)(diff * 1000.0f + P));
    }
}

__global__ void final_kernel(float* __restrict__ out) {
    out[0] = (float)(g_accum / (double)BATCH);
}

extern "C" void kernel_launch(void* const* d_in, const int* in_sizes, int n_in,
                              void* d_out, int out_size)
{
    const int*   x0 = nullptr;  const int*   ts = nullptr;
    const float* un = nullptr;  const float* W  = nullptr;
    const float* bi = nullptr;  const float* te = nullptr;
    for (int i = 0; i < n_in; i++) {
        switch (in_sizes[i]) {
            case BATCH * FEAT:   x0 = (const int*)d_in[i];   break;
            case BATCH:          ts = (const int*)d_in[i];   break;
            case BATCH * DCOLS:  un = (const float*)d_in[i]; break;
            case DCOLS * DCOLS:  W  = (const float*)d_in[i]; break;
            case DCOLS:          bi = (const float*)d_in[i]; break;
            case NT * DCOLS:     te = (const float*)d_in[i]; break;
            default: break;
        }
    }
    float* out = (float*)d_out;

    dim3 gcs(4, 16);
    wcs_kernel<<<gcs, 128>>>(W);          // fp16 W + partial colsums
    sched_comb_kernel<<<5, 1024>>>();     // schedule + colsum combine + zero accum
    ddpm_kernel<<<BATCH, 128>>>(x0, ts, un, bi, te);
    final_kernel<<<1, 1>>>(out);
}